// round 2
// baseline (speedup 1.0000x reference)
#include <cuda_runtime.h>
#include <cstdint>

// SimpleGNN: 3x CGConv + mean-pool + linear.
// z@Wf.T factors into node-level projections (dst-part, src-part) computed by one
// [N,128]x[128,512] GEMM per layer, plus a tiny K=16 edge-attr projection fused
// into the edge kernel. Edge kernel: warp/edge, gathers 4x512B rows of P,
// sigmoid*softplus, red.global.add.v4.f32 scatter into msg[dst].

#define NN 50000
#define EE 800000
#define CC 128
#define ZP 512

__device__ float g_P[(size_t)NN * ZP];     // node projections (102.4 MB)
__device__ float g_hA[(size_t)NN * CC];
__device__ float g_hB[(size_t)NN * CC];
__device__ float g_msg[(size_t)NN * CC];
__device__ float g_B[ZP * CC];             // packed node-projection weights
__device__ float g_cs[CC];                 // column sums for pooling
__device__ int   g_idx64;                  // 1 if edge_idx is int64, 0 if int32

// ---------------------------------------------------------------------------
// Detect index dtype. Probes only int64-slots [0,64) which are in-bounds for
// both layouts (int32 buffer = E int64-slots, int64 buffer = 2E slots).
// If data is int32, an int64 view packs two random indices -> high word != 0
// w.h.p. -> value outside [0,N) -> classified int32.
__global__ void detect_k(const long long* __restrict__ e64, int N) {
    if (threadIdx.x == 0 && blockIdx.x == 0) {
        int ok64 = 1;
        for (int i = 0; i < 64; i++) {
            long long v = e64[i];
            if (v < 0 || v >= N) { ok64 = 0; break; }
        }
        g_idx64 = ok64;
    }
}

// ---------------------------------------------------------------------------
// pack the 512x128 node-projection weight matrix:
// rows   0..127 : Wf[:,   0:128]  (dst part of f-gate)
// rows 128..255 : Wf[:, 128:256]  (src part of f-gate)
// rows 256..383 : Ws[:,   0:128]  (dst part of s-gate)
// rows 384..511 : Ws[:, 128:256]  (src part of s-gate)
__global__ void pack_B(const float* __restrict__ Wf, const float* __restrict__ Ws) {
    int j = blockIdx.x * blockDim.x + threadIdx.x;
    if (j >= ZP * CC) return;
    int row  = j >> 7;       // 0..511
    int k    = j & 127;
    int c    = row & 127;
    int part = row >> 7;     // 0..3
    const float* W = (part < 2) ? Wf : Ws;
    int off = (part & 1) ? 128 : 0;
    g_B[j] = W[c * 272 + off + k];
}

// ---------------------------------------------------------------------------
// P[M,512] = H[M,128] @ g_B^T ; fp32 tiled 64x64, 256 threads, 4x4 per thread
__global__ void gemm_k(const float* __restrict__ H, int M) {
    __shared__ float As[32][65];
    __shared__ float Bs[32][65];
    int tid = threadIdx.x;
    int tx = tid & 15, ty = tid >> 4;
    int i0 = blockIdx.x * 64, j0 = blockIdx.y * 64;

    float acc[4][4];
#pragma unroll
    for (int r = 0; r < 4; r++)
#pragma unroll
        for (int p = 0; p < 4; p++) acc[r][p] = 0.f;

    for (int k0 = 0; k0 < 128; k0 += 32) {
#pragma unroll
        for (int rep = 0; rep < 2; rep++) {
            int ii = (tid >> 3) + rep * 32;       // 0..63
            int kk = (tid & 7) << 2;              // 0,4,...,28
            int row = i0 + ii;
            float4 va = make_float4(0.f, 0.f, 0.f, 0.f);
            if (row < M) va = *(const float4*)(H + (size_t)row * 128 + k0 + kk);
            As[kk + 0][ii] = va.x; As[kk + 1][ii] = va.y;
            As[kk + 2][ii] = va.z; As[kk + 3][ii] = va.w;
            float4 vb = *(const float4*)(g_B + (size_t)(j0 + ii) * 128 + k0 + kk);
            Bs[kk + 0][ii] = vb.x; Bs[kk + 1][ii] = vb.y;
            Bs[kk + 2][ii] = vb.z; Bs[kk + 3][ii] = vb.w;
        }
        __syncthreads();
#pragma unroll
        for (int kk = 0; kk < 32; kk++) {
            float a[4], b[4];
#pragma unroll
            for (int r = 0; r < 4; r++) a[r] = As[kk][ty * 4 + r];
#pragma unroll
            for (int p = 0; p < 4; p++) b[p] = Bs[kk][tx * 4 + p];
#pragma unroll
            for (int r = 0; r < 4; r++)
#pragma unroll
                for (int p = 0; p < 4; p++) acc[r][p] = fmaf(a[r], b[p], acc[r][p]);
        }
        __syncthreads();
    }
#pragma unroll
    for (int r = 0; r < 4; r++) {
        int row = i0 + ty * 4 + r;
        if (row < M)
            *(float4*)(g_P + (size_t)row * ZP + j0 + tx * 4) =
                make_float4(acc[r][0], acc[r][1], acc[r][2], acc[r][3]);
    }
}

// ---------------------------------------------------------------------------
__global__ void zero_k(float* __restrict__ p, int n4) {
    float4* q = (float4*)p;
    for (int i = blockIdx.x * blockDim.x + threadIdx.x; i < n4;
         i += gridDim.x * blockDim.x)
        q[i] = make_float4(0.f, 0.f, 0.f, 0.f);
}

__device__ __forceinline__ float sigm(float x) {
    return __fdividef(1.f, 1.f + __expf(-x));
}
__device__ __forceinline__ float sftp(float x) {
    return fmaxf(x, 0.f) + __logf(1.f + __expf(-fabsf(x)));
}

// ---------------------------------------------------------------------------
// one warp per edge; lane l owns channels 4l..4l+3
__global__ void edge_k(const void* __restrict__ eidx_raw,
                       const float* __restrict__ ew,
                       const float* __restrict__ Wf, const float* __restrict__ Ws,
                       const float* __restrict__ bf, const float* __restrict__ bs,
                       int E) {
    __shared__ float4 wfe[16][32];   // [k][lane] = Wf[4l..4l+3][256+k]
    __shared__ float4 wse[16][32];
    __shared__ float4 bfv[32], bsv[32];
    int tid = threadIdx.x;
    for (int idx = tid; idx < 512; idx += blockDim.x) {
        int k = idx >> 5, l = idx & 31, c0 = l << 2;
        wfe[k][l] = make_float4(Wf[(c0 + 0) * 272 + 256 + k],
                                Wf[(c0 + 1) * 272 + 256 + k],
                                Wf[(c0 + 2) * 272 + 256 + k],
                                Wf[(c0 + 3) * 272 + 256 + k]);
        wse[k][l] = make_float4(Ws[(c0 + 0) * 272 + 256 + k],
                                Ws[(c0 + 1) * 272 + 256 + k],
                                Ws[(c0 + 2) * 272 + 256 + k],
                                Ws[(c0 + 3) * 272 + 256 + k]);
    }
    if (tid < 32) {
        bfv[tid] = *(const float4*)(bf + tid * 4);
        bsv[tid] = *(const float4*)(bs + tid * 4);
    }
    __syncthreads();

    const int is64 = g_idx64;
    const long long* e64 = (const long long*)eidx_raw;
    const int*       e32 = (const int*)eidx_raw;

    int lane = tid & 31;
    int warp = blockIdx.x * (blockDim.x >> 5) + (tid >> 5);
    int nw   = gridDim.x * (blockDim.x >> 5);
    float4 bF = bfv[lane], bS = bsv[lane];

    for (int e = warp; e < E; e += nw) {
        int s, d;
        if (is64) {
            s = (int)__ldg(e64 + e);
            d = (int)__ldg(e64 + E + e);
        } else {
            s = __ldg(e32 + e);
            d = __ldg(e32 + E + e);
        }
        const float4* ewp = (const float4*)(ew + (size_t)e * 16);
        float4 e0 = ewp[0], e1 = ewp[1], e2 = ewp[2], e3 = ewp[3];
        float ev[16] = {e0.x, e0.y, e0.z, e0.w, e1.x, e1.y, e1.z, e1.w,
                        e2.x, e2.y, e2.z, e2.w, e3.x, e3.y, e3.z, e3.w};

        const float* Pd = g_P + (size_t)d * ZP;
        const float* Ps = g_P + (size_t)s * ZP;
        float4 fd = *(const float4*)(Pd + lane * 4);
        float4 fs = *(const float4*)(Ps + 128 + lane * 4);
        float4 sd = *(const float4*)(Pd + 256 + lane * 4);
        float4 ss = *(const float4*)(Ps + 384 + lane * 4);

        float4 F, S;
        F.x = fd.x + fs.x + bF.x; F.y = fd.y + fs.y + bF.y;
        F.z = fd.z + fs.z + bF.z; F.w = fd.w + fs.w + bF.w;
        S.x = sd.x + ss.x + bS.x; S.y = sd.y + ss.y + bS.y;
        S.z = sd.z + ss.z + bS.z; S.w = sd.w + ss.w + bS.w;

#pragma unroll
        for (int k = 0; k < 16; k++) {
            float w = ev[k];
            float4 a = wfe[k][lane];
            F.x = fmaf(w, a.x, F.x); F.y = fmaf(w, a.y, F.y);
            F.z = fmaf(w, a.z, F.z); F.w = fmaf(w, a.w, F.w);
            float4 b = wse[k][lane];
            S.x = fmaf(w, b.x, S.x); S.y = fmaf(w, b.y, S.y);
            S.z = fmaf(w, b.z, S.z); S.w = fmaf(w, b.w, S.w);
        }
        float4 m;
        m.x = sigm(F.x) * sftp(S.x);
        m.y = sigm(F.y) * sftp(S.y);
        m.z = sigm(F.z) * sftp(S.z);
        m.w = sigm(F.w) * sftp(S.w);

        float* outp = g_msg + (size_t)d * CC + lane * 4;
        asm volatile("red.global.add.v4.f32 [%0], {%1,%2,%3,%4};"
                     :: "l"(outp), "f"(m.x), "f"(m.y), "f"(m.z), "f"(m.w)
                     : "memory");
    }
}

// ---------------------------------------------------------------------------
__global__ void combine_k(const float* __restrict__ h, float* __restrict__ o,
                          int n4, int relu) {
    const float4* h4 = (const float4*)h;
    const float4* m4 = (const float4*)g_msg;
    float4* o4 = (float4*)o;
    for (int i = blockIdx.x * blockDim.x + threadIdx.x; i < n4;
         i += gridDim.x * blockDim.x) {
        float4 a = h4[i], b = m4[i];
        a.x += b.x; a.y += b.y; a.z += b.z; a.w += b.w;
        if (relu) {
            a.x = fmaxf(a.x, 0.f); a.y = fmaxf(a.y, 0.f);
            a.z = fmaxf(a.z, 0.f); a.w = fmaxf(a.w, 0.f);
        }
        o4[i] = a;
    }
}

__global__ void colsum_k(const float* __restrict__ h, int M) {
    int c = threadIdx.x;   // 128 threads
    float loc = 0.f;
    for (int i = blockIdx.x; i < M; i += gridDim.x)
        loc += h[(size_t)i * CC + c];
    atomicAdd(&g_cs[c], loc);
}

__global__ void final_k(const float* __restrict__ Wlin,
                        const float* __restrict__ blin,
                        float* __restrict__ out, float invM) {
    int o = threadIdx.x;
    if (o < 64) {
        float a = 0.f;
#pragma unroll 4
        for (int c = 0; c < 128; c++) a += g_cs[c] * Wlin[o * 128 + c];
        out[o] = blin[o] + a * invM;
    }
}

// ---------------------------------------------------------------------------
extern "C" void kernel_launch(void* const* d_in, const int* in_sizes, int n_in,
                              void* d_out, int out_size) {
    const float* x    = (const float*)d_in[0];
    const void*  eidx = d_in[1];
    const float* ew   = (const float*)d_in[2];
    const float* Wf[3] = {(const float*)d_in[3], (const float*)d_in[7],  (const float*)d_in[11]};
    const float* bf[3] = {(const float*)d_in[4], (const float*)d_in[8],  (const float*)d_in[12]};
    const float* Ws[3] = {(const float*)d_in[5], (const float*)d_in[9],  (const float*)d_in[13]};
    const float* bs[3] = {(const float*)d_in[6], (const float*)d_in[10], (const float*)d_in[14]};
    const float* Wlin = (const float*)d_in[15];
    const float* blin = (const float*)d_in[16];
    float* out = (float*)d_out;

    int M = in_sizes[0] / 128;   // 50000
    int E = in_sizes[2] / 16;    // 800000

    float *hA, *hB, *msg, *cs;
    cudaGetSymbolAddress((void**)&hA,  g_hA);
    cudaGetSymbolAddress((void**)&hB,  g_hB);
    cudaGetSymbolAddress((void**)&msg, g_msg);
    cudaGetSymbolAddress((void**)&cs,  g_cs);

    const float* hin[3]  = {x, hA, hB};
    float*       hout[3] = {hA, hB, hA};

    dim3 ggrid((M + 63) / 64, 8);
    int n4 = M * CC / 4;

    detect_k<<<1, 32>>>((const long long*)eidx, M);

    for (int l = 0; l < 3; l++) {
        pack_B<<<(ZP * CC + 255) / 256, 256>>>(Wf[l], Ws[l]);
        gemm_k<<<ggrid, 256>>>(hin[l], M);
        zero_k<<<1024, 256>>>(msg, n4);
        edge_k<<<1184, 256>>>(eidx, ew, Wf[l], Ws[l], bf[l], bs[l], E);
        combine_k<<<1024, 256>>>(hin[l], hout[l], n4, (l < 2) ? 1 : 0);
    }
    zero_k<<<1, 32>>>(cs, CC / 4);
    colsum_k<<<512, 128>>>(hA, M);
    final_k<<<1, 64>>>(Wlin, blin, out, 1.0f / (float)M);
}